// round 14
// baseline (speedup 1.0000x reference)
#include <cuda_runtime.h>
#include <cuda_bf16.h>
#include <cuda_fp16.h>
#include <math.h>
#include <stdint.h>

#define B_ROWS 8192
#define DIM    4096
#define NPH    128
#define LN_EPS 1e-5f
#define PI_F   3.14159265358979323846f
#define NSEG   6                      // 3 segment-pairs x 2 k-halves

// ---------------- scratch (device globals) ----------------------------------
__device__ __half g_xh [(size_t)B_ROWS * DIM];          // x hi  fp16
__device__ __half g_xl [(size_t)B_ROWS * DIM];          // x lo  fp16
__device__ __half g_wkqh[(size_t)NPH * DIM];            // [Wk;Wq] hi fp16
__device__ __half g_wkql[(size_t)NPH * DIM];            // [Wk;Wq] lo fp16
__device__ __half g_wvh[(size_t)DIM * DIM];             // Wv  fp16
__device__ __half g_woh[(size_t)DIM * DIM];             // Wo  fp16
__device__ __half g_vh [(size_t)B_ROWS * DIM];          // (V+bv)*coef fp16
__device__ __half g_nh [(size_t)B_ROWS * DIM];          // normed fp16
__device__ float g_phase[NSEG * (size_t)B_ROWS * NPH];  // 6 split-K partials
__device__ float g_coef[B_ROWS];

// ---------------- PTX helpers ------------------------------------------------
__device__ __forceinline__ void cp_async16s(uint32_t s, const void* gmem) {
    asm volatile("cp.async.cg.shared.global [%0], [%1], 16;\n" :: "r"(s), "l"(gmem));
}
__device__ __forceinline__ void cp_commit() { asm volatile("cp.async.commit_group;\n"); }
template <int N> __device__ __forceinline__ void cp_wait() {
    asm volatile("cp.async.wait_group %0;\n" :: "n"(N));
}
__device__ __forceinline__ void ldmx4(uint32_t& r0, uint32_t& r1, uint32_t& r2, uint32_t& r3,
                                      uint32_t addr) {
    asm volatile("ldmatrix.sync.aligned.m8n8.x4.shared.b16 {%0,%1,%2,%3}, [%4];"
                 : "=r"(r0), "=r"(r1), "=r"(r2), "=r"(r3) : "r"(addr));
}
__device__ __forceinline__ void mma_f16(float* c, uint32_t a0, uint32_t a1,
                                        uint32_t a2, uint32_t a3,
                                        uint32_t b0, uint32_t b1) {
    asm volatile("mma.sync.aligned.m16n8k16.row.col.f32.f16.f16.f32 "
                 "{%0,%1,%2,%3}, {%4,%5,%6,%7}, {%8,%9}, {%0,%1,%2,%3};"
                 : "+f"(c[0]), "+f"(c[1]), "+f"(c[2]), "+f"(c[3])
                 : "r"(a0), "r"(a1), "r"(a2), "r"(a3), "r"(b0), "r"(b1));
}
__device__ __forceinline__ uint32_t smem_u32(const void* p) {
    uint32_t a;
    asm("{ .reg .u64 t; cvta.to.shared.u64 t, %1; cvt.u32.u64 %0, t; }" : "=r"(a) : "l"(p));
    return a;
}

// --------- x prep: one read -> fp16 hi + fp16 lo ------------------------------
__global__ void prep_x(const float* __restrict__ in, size_t n_vec4) {
    size_t i = (size_t)blockIdx.x * blockDim.x + threadIdx.x;
    if (i >= n_vec4) return;
    size_t e = i * 4;
    float4 v = *reinterpret_cast<const float4*>(in + e);
    float vv[4] = {v.x, v.y, v.z, v.w};
    union { __half h[4]; uint2 u; } H, L;
#pragma unroll
    for (int q = 0; q < 4; q++) {
        H.h[q] = __float2half_rn(vv[q]);
        L.h[q] = __float2half_rn(vv[q] - __half2float(H.h[q]));
    }
    *reinterpret_cast<uint2*>(g_xh + e) = H.u;
    *reinterpret_cast<uint2*>(g_xl + e) = L.u;
}

// ------- merged weight split hi/lo for Wk and Wq (one launch) ----------------
__global__ void split2_kq(const float* __restrict__ Wk, const float* __restrict__ Wq,
                          size_t n_vec4_each) {
    size_t i = (size_t)blockIdx.x * blockDim.x + threadIdx.x;
    if (i >= 2 * n_vec4_each) return;
    const float* in = (i < n_vec4_each) ? Wk : Wq;
    size_t base = (i < n_vec4_each) ? 0 : (size_t)64 * DIM;
    size_t li = (i < n_vec4_each) ? i : (i - n_vec4_each);
    size_t e = li * 4;
    float4 v = *reinterpret_cast<const float4*>(in + e);
    float vv[4] = {v.x, v.y, v.z, v.w};
    union { __half h[4]; uint2 u; } H, L;
#pragma unroll
    for (int q = 0; q < 4; q++) {
        H.h[q] = __float2half_rn(vv[q]);
        L.h[q] = __float2half_rn(vv[q] - __half2float(H.h[q]));
    }
    *reinterpret_cast<uint2*>(g_wkqh + base + e) = H.u;
    *reinterpret_cast<uint2*>(g_wkql + base + e) = L.u;
}

// ------- merged fp32 -> fp16 convert for Wv and Wo (one launch) --------------
__global__ void conv_w2(const float* __restrict__ Wv, const float* __restrict__ Wo,
                        size_t n_vec4_each) {
    size_t i = (size_t)blockIdx.x * blockDim.x + threadIdx.x;
    if (i >= 2 * n_vec4_each) return;
    const float* in = (i < n_vec4_each) ? Wv : Wo;
    __half* out     = (i < n_vec4_each) ? g_wvh : g_woh;
    size_t li = (i < n_vec4_each) ? i : (i - n_vec4_each);
    float4 v = *reinterpret_cast<const float4*>(in + li * 4);
    __half2 h0 = __floats2half2_rn(v.x, v.y);
    __half2 h1 = __floats2half2_rn(v.z, v.w);
    uint2 u = {*reinterpret_cast<uint32_t*>(&h0), *reinterpret_cast<uint32_t*>(&h1)};
    *reinterpret_cast<uint2*>(out + li * 4) = u;
}

// ---------------- per-row phase alignment -> coef (sums 6 partials) ----------
__global__ void coef_kernel(const float* __restrict__ bk, const float* __restrict__ bq) {
    int row  = blockIdx.x * 8 + (threadIdx.x >> 5);
    int lane = threadIdx.x & 31;
    const size_t SEG = (size_t)B_ROWS * NPH;
    const float* ph = &g_phase[(size_t)row * NPH];
    float s = 0.f;
#pragma unroll
    for (int p = lane; p < 64; p += 32) {
        float rk = 0.f, rq = 0.f;
#pragma unroll
        for (int t = 0; t < NSEG; t++) {
            rk += ph[t * SEG + p];
            rq += ph[t * SEG + 64 + p];
        }
        float kp = tanhf(rk + bk[p]) * PI_F;
        float qp = tanhf(rq + bq[p]) * PI_F;
        s += cosf(kp - qp);
    }
#pragma unroll
    for (int o = 16; o; o >>= 1) s += __shfl_xor_sync(0xffffffffu, s, o);
    if (lane == 0) {
        float gain = log1pf(expf(s * (1.0f / 64.0f) + 0.5f));
        g_coef[row] = s * gain * (1.0f / 64.0f);
    }
}

// ------- LayerNorm: fp16 in ((V+bv)*coef), fp16 out --------------------------
__global__ __launch_bounds__(256) void ln_kernel(const float* __restrict__ ln_g,
                                                 const float* __restrict__ ln_b) {
    int row = blockIdx.x;
    const __half* vr = g_vh + (size_t)row * DIM;
    __half* nr = g_nh + (size_t)row * DIM;
    int tid = threadIdx.x;

    float vals[16];
    float sum = 0.f, sq = 0.f;
#pragma unroll
    for (int j = 0; j < 4; j++) {
        int k = (tid + j * 256) * 4;
        uint2 u = *reinterpret_cast<const uint2*>(vr + k);
        __half2 h0 = *reinterpret_cast<__half2*>(&u.x);
        __half2 h1 = *reinterpret_cast<__half2*>(&u.y);
        float2 f0 = __half22float2(h0);
        float2 f1 = __half22float2(h1);
        vals[j*4+0]=f0.x; vals[j*4+1]=f0.y; vals[j*4+2]=f1.x; vals[j*4+3]=f1.y;
        sum += f0.x+f0.y+f1.x+f1.y;
        sq  += f0.x*f0.x+f0.y*f0.y+f1.x*f1.x+f1.y*f1.y;
    }
    __shared__ float s1[8], s2[8];
#pragma unroll
    for (int o = 16; o; o >>= 1) {
        sum += __shfl_xor_sync(0xffffffffu, sum, o);
        sq  += __shfl_xor_sync(0xffffffffu, sq,  o);
    }
    int warp = tid >> 5, lane = tid & 31;
    if (lane == 0) { s1[warp] = sum; s2[warp] = sq; }
    __syncthreads();
    sum = 0.f; sq = 0.f;
#pragma unroll
    for (int w = 0; w < 8; w++) { sum += s1[w]; sq += s2[w]; }

    float mu   = sum * (1.0f / DIM);
    float var  = sq * (1.0f / DIM) - mu * mu;
    float rstd = rsqrtf(var + LN_EPS);
#pragma unroll
    for (int j = 0; j < 4; j++) {
        int k = (tid + j * 256) * 4;
        float4 g = *reinterpret_cast<const float4*>(ln_g + k);
        float4 bb = *reinterpret_cast<const float4*>(ln_b + k);
        __half2 h0 = __floats2half2_rn((vals[j*4+0]-mu)*rstd*g.x + bb.x,
                                       (vals[j*4+1]-mu)*rstd*g.y + bb.y);
        __half2 h1 = __floats2half2_rn((vals[j*4+2]-mu)*rstd*g.z + bb.z,
                                       (vals[j*4+3]-mu)*rstd*g.w + bb.w);
        uint2 u = {*reinterpret_cast<uint32_t*>(&h0), *reinterpret_cast<uint32_t*>(&h1)};
        *reinterpret_cast<uint2*>(nr + k) = u;
    }
}

// ================= GEMM geometry =============================================
constexpr int BM = 128, BN = 128, BK = 64;
constexpr int STAGES = 3;
constexpr int TILE_B = 128 * 128;
constexpr size_t GEMM_SMEM = (size_t)STAGES * 2 * TILE_B; // 98304

// phase: BM=64
constexpr int PBM = 64;
constexpr int P_AST = PBM * 128;                  // 8192 B
constexpr int P_BST = NPH * 128;                  // 16384 B
constexpr int P_STAGE = P_AST + P_BST;            // 24576 B
constexpr size_t PH_SMEM = (size_t)STAGES * P_STAGE;  // 73728

// ======== phase GEMM: fp16x3, BM=64 x BN=128, 6-way split (seg x k-half) ======
// blockIdx.y = t in [0,6): seg = t>>1 (0:Ah*Bh 1:Ah*Bl 2:Al*Bh), khalf = t&1
__global__ __launch_bounds__(256, 2) void gemm_phase(
    float* __restrict__ C, int M, int K)
{
    extern __shared__ __align__(128) unsigned char dsmem[];
    uint32_t sb = smem_u32(dsmem);

    int t = blockIdx.y;
    int seg = t >> 1;
    int khalf = t & 1;
    const __half* A  = (seg == 2) ? g_xl : g_xh;
    const __half* Bw = (seg == 1) ? g_wkql : g_wkqh;
    C += (size_t)t * (size_t)M * NPH;
    const int KH = K / 2;                       // 2048
    size_t kbase = (size_t)khalf * KH;

    int tid  = threadIdx.x;
    int warp = tid >> 5;
    int lane = tid & 31;

    int m0 = blockIdx.x * PBM;
    int wm = (warp & 1) * 32;
    int wn = (warp >> 1) * 32;

    int chunk = tid & 7;
    int row0  = tid >> 3;
    const __half* gA = A  + (size_t)m0 * DIM + kbase + chunk * 8;
    const __half* gB = Bw + kbase + chunk * 8;

    auto load_tile = [&](int kt, int stg) {
        size_t koff = (size_t)kt * BK;
        uint32_t dA = sb + stg * P_STAGE;
        uint32_t dB = dA + P_AST;
#pragma unroll
        for (int p = 0; p < 2; p++) {
            int r = row0 + p * 32;
            uint32_t so = r * 128 + ((chunk * 16) ^ ((r & 7) << 4));
            cp_async16s(dA + so, gA + (size_t)r * DIM + koff);
        }
#pragma unroll
        for (int p = 0; p < 4; p++) {
            int r = row0 + p * 32;
            uint32_t so = r * 128 + ((chunk * 16) ^ ((r & 7) << 4));
            cp_async16s(dB + so, gB + (size_t)r * DIM + koff);
        }
    };

    int lr = lane & 15;
    int kb = lane >> 4;
    uint32_t xv = (uint32_t)((lr & 7) << 4);
    uint32_t aRow0 = (uint32_t)(wm + lr) * 128;
    uint32_t bRow0 = (uint32_t)(wn + lr) * 128;

    float acc[2][4][4];
#pragma unroll
    for (int i = 0; i < 2; i++)
#pragma unroll
        for (int j = 0; j < 4; j++)
#pragma unroll
            for (int q = 0; q < 4; q++) acc[i][j][q] = 0.f;

    const int nt = KH / BK;   // 32
#pragma unroll
    for (int s = 0; s < STAGES - 1; s++) { load_tile(s, s); cp_commit(); }

    for (int it = 0; it < nt; it++) {
        cp_wait<STAGES - 2>();
        __syncthreads();
        int pre = it + STAGES - 1;
        if (pre < nt) { load_tile(pre, pre % STAGES); cp_commit(); }

        uint32_t tA = sb + (it % STAGES) * P_STAGE;
        uint32_t tB = tA + P_AST;
#pragma unroll
        for (int s16 = 0; s16 < 4; s16++) {
            uint32_t col = (uint32_t)((s16 * 32 + kb * 16)) ^ xv;
            uint32_t a[2][4];
#pragma unroll
            for (int mi = 0; mi < 2; mi++)
                ldmx4(a[mi][0], a[mi][1], a[mi][2], a[mi][3],
                      tA + aRow0 + (uint32_t)(mi * 16 * 128) + col);
            uint32_t b[2][4];
#pragma unroll
            for (int nb = 0; nb < 2; nb++)
                ldmx4(b[nb][0], b[nb][1], b[nb][2], b[nb][3],
                      tB + bRow0 + (uint32_t)(nb * 16 * 128) + col);
#pragma unroll
            for (int mi = 0; mi < 2; mi++)
#pragma unroll
                for (int nb = 0; nb < 2; nb++) {
                    mma_f16(acc[mi][nb * 2 + 0], a[mi][0], a[mi][1], a[mi][2], a[mi][3],
                            b[nb][0], b[nb][2]);
                    mma_f16(acc[mi][nb * 2 + 1], a[mi][0], a[mi][1], a[mi][2], a[mi][3],
                            b[nb][1], b[nb][3]);
                }
        }
    }
    cp_wait<0>();

    int mrow = m0 + wm + (lane >> 2);
    int ncol = wn + (lane & 3) * 2;
#pragma unroll
    for (int mi = 0; mi < 2; mi++) {
#pragma unroll
        for (int nj = 0; nj < 4; nj++) {
            int n = ncol + nj * 8;
            size_t go0 = (size_t)(mrow + mi * 16)     * NPH + n;
            size_t go1 = (size_t)(mrow + mi * 16 + 8) * NPH + n;
            *reinterpret_cast<float2*>(C + go0) = {acc[mi][nj][0], acc[mi][nj][1]};
            *reinterpret_cast<float2*>(C + go1) = {acc[mi][nj][2], acc[mi][nj][3]};
        }
    }
}

// ======== big GEMM: raw mma.sync fp16, 128x128, 2 CTA/SM =====================
// MODE 1: Cf[go] = acc + bias[n] + (float)addend_h[go]
// MODE 2: Ch[go] = (__half)((acc + bias[n]) * coef[m])
template <int MODE>
__global__ __launch_bounds__(256, 2) void gemm_big(
    const __half* __restrict__ A, const __half* __restrict__ Bw,
    float* __restrict__ Cf, __half* __restrict__ Ch, int M, int N, int K,
    const float* __restrict__ bias, const __half* __restrict__ addend_h,
    const float* __restrict__ coef)
{
    extern __shared__ __align__(128) unsigned char dsmem[];
    uint32_t sb = smem_u32(dsmem);
    uint32_t sA = sb;
    uint32_t sB = sb + STAGES * TILE_B;

    int tid  = threadIdx.x;
    int warp = tid >> 5;
    int lane = tid & 31;

    const int num_m = M / BM, num_n = N / BN;
    const int GROUP = 8;
    int id = blockIdx.x;
    int group_size = GROUP * num_n;
    int gid = id / group_size;
    int first_m = gid * GROUP;
    int gm_sz = (num_m - first_m) < GROUP ? (num_m - first_m) : GROUP;
    int pid_m = first_m + (id % group_size) % gm_sz;
    int pid_n = (id % group_size) / gm_sz;
    int m0 = pid_m * BM;
    int n0 = pid_n * BN;

    int wm = (warp & 3) * 32;
    int wn = (warp >> 2) * 64;

    int chunk = tid & 7;
    int row0  = tid >> 3;
    const __half* gA = A  + (size_t)m0 * K + chunk * 8;
    const __half* gB = Bw + (size_t)n0 * K + chunk * 8;

    auto load_tile = [&](int kt, int stg) {
        size_t koff = (size_t)kt * BK;
        uint32_t dA = sA + stg * TILE_B;
        uint32_t dB = sB + stg * TILE_B;
#pragma unroll
        for (int p = 0; p < 4; p++) {
            int r = row0 + p * 32;
            uint32_t so = r * 128 + ((chunk * 16) ^ ((r & 7) << 4));
            cp_async16s(dA + so, gA + (size_t)r * K + koff);
            cp_async16s(dB + so, gB + (size_t)r * K + koff);
        }
    };

    int lr = lane & 15;
    int kb = lane >> 4;
    uint32_t xv = (uint32_t)((lr & 7) << 4);
    uint32_t aRow0 = (uint32_t)(wm + lr) * 128;
    uint32_t bRow0 = (uint32_t)(wn + lr) * 128;

    float acc[2][8][4];
#pragma unroll
    for (int i = 0; i < 2; i++)
#pragma unroll
        for (int j = 0; j < 8; j++)
#pragma unroll
            for (int q = 0; q < 4; q++) acc[i][j][q] = 0.f;

    const int nt = K / BK;
#pragma unroll
    for (int s = 0; s < STAGES - 1; s++) { load_tile(s, s); cp_commit(); }

    for (int it = 0; it < nt; it++) {
        cp_wait<STAGES - 2>();
        __syncthreads();
        int pre = it + STAGES - 1;
        if (pre < nt) { load_tile(pre, pre % STAGES); cp_commit(); }

        uint32_t tA = sA + (it % STAGES) * TILE_B;
        uint32_t tB = sB + (it % STAGES) * TILE_B;
#pragma unroll
        for (int s16 = 0; s16 < 4; s16++) {
            uint32_t col = (uint32_t)((s16 * 32 + kb * 16)) ^ xv;
            uint32_t a[2][4];
#pragma unroll
            for (int mi = 0; mi < 2; mi++)
                ldmx4(a[mi][0], a[mi][1], a[mi][2], a[mi][3],
                      tA + aRow0 + (uint32_t)(mi * 16 * 128) + col);
            uint32_t b[4][4];
#pragma unroll
            for (int nb = 0; nb < 4; nb++)
                ldmx4(b[nb][0], b[nb][1], b[nb][2], b[nb][3],
                      tB + bRow0 + (uint32_t)(nb * 16 * 128) + col);
#pragma unroll
            for (int mi = 0; mi < 2; mi++)
#pragma unroll
                for (int nb = 0; nb < 4; nb++) {
                    mma_f16(acc[mi][nb * 2 + 0], a[mi][0], a[mi][1], a[mi][2], a[mi][3],
                            b[nb][0], b[nb][2]);
                    mma_f16(acc[mi][nb * 2 + 1], a[mi][0], a[mi][1], a[mi][2], a[mi][3],
                            b[nb][1], b[nb][3]);
                }
        }
    }
    cp_wait<0>();

    int mrow = m0 + wm + (lane >> 2);
    int ncol = n0 + wn + (lane & 3) * 2;
#pragma unroll
    for (int mi = 0; mi < 2; mi++) {
        float cf0 = 0.f, cf1 = 0.f;
        if (MODE == 2) {
            cf0 = coef[mrow + mi * 16];
            cf1 = coef[mrow + mi * 16 + 8];
        }
#pragma unroll
        for (int nj = 0; nj < 8; nj++) {
            int n = ncol + nj * 8;
            size_t go0 = (size_t)(mrow + mi * 16)     * N + n;
            size_t go1 = (size_t)(mrow + mi * 16 + 8) * N + n;
            float2 bb = *reinterpret_cast<const float2*>(bias + n);
            if (MODE == 1) {
                float2 a0 = __half22float2(*reinterpret_cast<const __half2*>(addend_h + go0));
                float2 a1 = __half22float2(*reinterpret_cast<const __half2*>(addend_h + go1));
                float2 v0 = {acc[mi][nj][0] + bb.x + a0.x, acc[mi][nj][1] + bb.y + a0.y};
                float2 v1 = {acc[mi][nj][2] + bb.x + a1.x, acc[mi][nj][3] + bb.y + a1.y};
                *reinterpret_cast<float2*>(Cf + go0) = v0;
                *reinterpret_cast<float2*>(Cf + go1) = v1;
            } else {
                __half2 h0 = __floats2half2_rn((acc[mi][nj][0] + bb.x) * cf0,
                                               (acc[mi][nj][1] + bb.y) * cf0);
                __half2 h1 = __floats2half2_rn((acc[mi][nj][2] + bb.x) * cf1,
                                               (acc[mi][nj][3] + bb.y) * cf1);
                *reinterpret_cast<__half2*>(Ch + go0) = h0;
                *reinterpret_cast<__half2*>(Ch + go1) = h1;
            }
        }
    }
}

// ---------------- launch -----------------------------------------------------
extern "C" void kernel_launch(void* const* d_in, const int* in_sizes, int n_in,
                              void* d_out, int out_size) {
    const float* x    = (const float*)d_in[0];
    const float* Wk   = (const float*)d_in[1];
    const float* bk   = (const float*)d_in[2];
    const float* Wq   = (const float*)d_in[3];
    const float* bq   = (const float*)d_in[4];
    const float* Wv   = (const float*)d_in[5];
    const float* bv   = (const float*)d_in[6];
    const float* ln_g = (const float*)d_in[7];
    const float* ln_b = (const float*)d_in[8];
    const float* Wo   = (const float*)d_in[9];
    const float* bo   = (const float*)d_in[10];
    float* out = (float*)d_out;

    __half *p_xh, *p_wvh, *p_woh, *p_vh, *p_nh;
    float *p_phase, *p_coef;
    cudaGetSymbolAddress((void**)&p_xh,   g_xh);
    cudaGetSymbolAddress((void**)&p_wvh,  g_wvh);
    cudaGetSymbolAddress((void**)&p_woh,  g_woh);
    cudaGetSymbolAddress((void**)&p_vh,   g_vh);
    cudaGetSymbolAddress((void**)&p_nh,   g_nh);
    cudaGetSymbolAddress((void**)&p_phase, g_phase);
    cudaGetSymbolAddress((void**)&p_coef,  g_coef);

    cudaFuncSetAttribute((const void*)gemm_phase,
                         cudaFuncAttributeMaxDynamicSharedMemorySize, (int)PH_SMEM);
    cudaFuncSetAttribute((const void*)gemm_big<1>,
                         cudaFuncAttributeMaxDynamicSharedMemorySize, (int)GEMM_SMEM);
    cudaFuncSetAttribute((const void*)gemm_big<2>,
                         cudaFuncAttributeMaxDynamicSharedMemorySize, (int)GEMM_SMEM);

    // prep (3 launches)
    size_t nx = (size_t)B_ROWS * DIM / 4;
    prep_x<<<(unsigned)((nx + 255) / 256), 256>>>(x, nx);                          // 1
    size_t nw = (size_t)DIM * DIM / 4;
    conv_w2<<<(unsigned)((2 * nw + 255) / 256), 256>>>(Wv, Wo, nw);                // 2
    size_t nk = (size_t)64 * DIM / 4;
    split2_kq<<<(unsigned)((2 * nk + 255) / 256), 256>>>(Wk, Wq, nk);              // 3

    // phase scores (6-way split: 3 segment-pairs x 2 k-halves) -> coef
    gemm_phase<<<dim3(B_ROWS / PBM, NSEG), 256, PH_SMEM>>>(p_phase, B_ROWS, DIM);  // 4
    coef_kernel<<<B_ROWS / 8, 256>>>(bk, bq);                                      // 5

    // V path: g_vh = (x @ Wv^T + bv) * coef   (fp16)
    gemm_big<2><<<(B_ROWS / BM) * (DIM / BN), 256, GEMM_SMEM>>>(
        p_xh, p_wvh, nullptr, p_vh, B_ROWS, DIM, DIM, bv, nullptr, p_coef);        // 6

    // LayerNorm -> fp16 normed
    ln_kernel<<<B_ROWS, 256>>>(ln_g, ln_b);                                        // 7

    // out = x + normed @ Wo^T + bo   (x residual read as fp16)
    gemm_big<1><<<(B_ROWS / BM) * (DIM / BN), 256, GEMM_SMEM>>>(
        p_nh, p_woh, out, nullptr, B_ROWS, DIM, DIM, bo, p_xh, nullptr);           // 8
}

// round 15
// speedup vs baseline: 1.0097x; 1.0097x over previous
#include <cuda_runtime.h>
#include <cuda_bf16.h>
#include <cuda_fp16.h>
#include <math.h>
#include <stdint.h>

#define B_ROWS 8192
#define DIM    4096
#define NPH    128
#define LN_EPS 1e-5f
#define PI_F   3.14159265358979323846f
#define NSEG   2                      // split-K halves (fused segments)

// ---------------- scratch (device globals) ----------------------------------
__device__ __half g_xh [(size_t)B_ROWS * DIM];          // x hi  fp16
__device__ __half g_xl [(size_t)B_ROWS * DIM];          // x lo  fp16
__device__ __half g_wkqh[(size_t)NPH * DIM];            // [Wk;Wq] hi fp16
__device__ __half g_wkql[(size_t)NPH * DIM];            // [Wk;Wq] lo fp16
__device__ __half g_wvh[(size_t)DIM * DIM];             // Wv  fp16
__device__ __half g_woh[(size_t)DIM * DIM];             // Wo  fp16
__device__ __half g_vh [(size_t)B_ROWS * DIM];          // (V+bv)*coef fp16
__device__ __half g_nh [(size_t)B_ROWS * DIM];          // normed fp16
__device__ float g_phase[NSEG * (size_t)B_ROWS * NPH];  // split-K partials
__device__ float g_coef[B_ROWS];

// ---------------- PTX helpers ------------------------------------------------
__device__ __forceinline__ void cp_async16s(uint32_t s, const void* gmem) {
    asm volatile("cp.async.cg.shared.global [%0], [%1], 16;\n" :: "r"(s), "l"(gmem));
}
__device__ __forceinline__ void cp_commit() { asm volatile("cp.async.commit_group;\n"); }
template <int N> __device__ __forceinline__ void cp_wait() {
    asm volatile("cp.async.wait_group %0;\n" :: "n"(N));
}
__device__ __forceinline__ void ldmx4(uint32_t& r0, uint32_t& r1, uint32_t& r2, uint32_t& r3,
                                      uint32_t addr) {
    asm volatile("ldmatrix.sync.aligned.m8n8.x4.shared.b16 {%0,%1,%2,%3}, [%4];"
                 : "=r"(r0), "=r"(r1), "=r"(r2), "=r"(r3) : "r"(addr));
}
__device__ __forceinline__ void mma_f16(float* c, uint32_t a0, uint32_t a1,
                                        uint32_t a2, uint32_t a3,
                                        uint32_t b0, uint32_t b1) {
    asm volatile("mma.sync.aligned.m16n8k16.row.col.f32.f16.f16.f32 "
                 "{%0,%1,%2,%3}, {%4,%5,%6,%7}, {%8,%9}, {%0,%1,%2,%3};"
                 : "+f"(c[0]), "+f"(c[1]), "+f"(c[2]), "+f"(c[3])
                 : "r"(a0), "r"(a1), "r"(a2), "r"(a3), "r"(b0), "r"(b1));
}
__device__ __forceinline__ uint32_t smem_u32(const void* p) {
    uint32_t a;
    asm("{ .reg .u64 t; cvta.to.shared.u64 t, %1; cvt.u32.u64 %0, t; }" : "=r"(a) : "l"(p));
    return a;
}

// --------- x prep: one read -> fp16 hi + fp16 lo ------------------------------
__global__ void prep_x(const float* __restrict__ in, size_t n_vec4) {
    size_t i = (size_t)blockIdx.x * blockDim.x + threadIdx.x;
    if (i >= n_vec4) return;
    size_t e = i * 4;
    float4 v = *reinterpret_cast<const float4*>(in + e);
    float vv[4] = {v.x, v.y, v.z, v.w};
    union { __half h[4]; uint2 u; } H, L;
#pragma unroll
    for (int q = 0; q < 4; q++) {
        H.h[q] = __float2half_rn(vv[q]);
        L.h[q] = __float2half_rn(vv[q] - __half2float(H.h[q]));
    }
    *reinterpret_cast<uint2*>(g_xh + e) = H.u;
    *reinterpret_cast<uint2*>(g_xl + e) = L.u;
}

// ------- merged weight split hi/lo for Wk and Wq (one launch) ----------------
__global__ void split2_kq(const float* __restrict__ Wk, const float* __restrict__ Wq,
                          size_t n_vec4_each) {
    size_t i = (size_t)blockIdx.x * blockDim.x + threadIdx.x;
    if (i >= 2 * n_vec4_each) return;
    const float* in = (i < n_vec4_each) ? Wk : Wq;
    size_t base = (i < n_vec4_each) ? 0 : (size_t)64 * DIM;
    size_t li = (i < n_vec4_each) ? i : (i - n_vec4_each);
    size_t e = li * 4;
    float4 v = *reinterpret_cast<const float4*>(in + e);
    float vv[4] = {v.x, v.y, v.z, v.w};
    union { __half h[4]; uint2 u; } H, L;
#pragma unroll
    for (int q = 0; q < 4; q++) {
        H.h[q] = __float2half_rn(vv[q]);
        L.h[q] = __float2half_rn(vv[q] - __half2float(H.h[q]));
    }
    *reinterpret_cast<uint2*>(g_wkqh + base + e) = H.u;
    *reinterpret_cast<uint2*>(g_wkql + base + e) = L.u;
}

// ------- merged fp32 -> fp16 convert for Wv and Wo (one launch) --------------
__global__ void conv_w2(const float* __restrict__ Wv, const float* __restrict__ Wo,
                        size_t n_vec4_each) {
    size_t i = (size_t)blockIdx.x * blockDim.x + threadIdx.x;
    if (i >= 2 * n_vec4_each) return;
    const float* in = (i < n_vec4_each) ? Wv : Wo;
    __half* out     = (i < n_vec4_each) ? g_wvh : g_woh;
    size_t li = (i < n_vec4_each) ? i : (i - n_vec4_each);
    float4 v = *reinterpret_cast<const float4*>(in + li * 4);
    __half2 h0 = __floats2half2_rn(v.x, v.y);
    __half2 h1 = __floats2half2_rn(v.z, v.w);
    uint2 u = {*reinterpret_cast<uint32_t*>(&h0), *reinterpret_cast<uint32_t*>(&h1)};
    *reinterpret_cast<uint2*>(out + li * 4) = u;
}

// ---------------- per-row phase alignment -> coef (sums NSEG partials) -------
__global__ void coef_kernel(const float* __restrict__ bk, const float* __restrict__ bq) {
    int row  = blockIdx.x * 8 + (threadIdx.x >> 5);
    int lane = threadIdx.x & 31;
    const size_t SEG = (size_t)B_ROWS * NPH;
    const float* ph = &g_phase[(size_t)row * NPH];
    float s = 0.f;
#pragma unroll
    for (int p = lane; p < 64; p += 32) {
        float rk = 0.f, rq = 0.f;
#pragma unroll
        for (int t = 0; t < NSEG; t++) {
            rk += ph[t * SEG + p];
            rq += ph[t * SEG + 64 + p];
        }
        float kp = tanhf(rk + bk[p]) * PI_F;
        float qp = tanhf(rq + bq[p]) * PI_F;
        s += cosf(kp - qp);
    }
#pragma unroll
    for (int o = 16; o; o >>= 1) s += __shfl_xor_sync(0xffffffffu, s, o);
    if (lane == 0) {
        float gain = log1pf(expf(s * (1.0f / 64.0f) + 0.5f));
        g_coef[row] = s * gain * (1.0f / 64.0f);
    }
}

// ------- LayerNorm: fp16 in ((V+bv)*coef), fp16 out --------------------------
__global__ __launch_bounds__(256) void ln_kernel(const float* __restrict__ ln_g,
                                                 const float* __restrict__ ln_b) {
    int row = blockIdx.x;
    const __half* vr = g_vh + (size_t)row * DIM;
    __half* nr = g_nh + (size_t)row * DIM;
    int tid = threadIdx.x;

    float vals[16];
    float sum = 0.f, sq = 0.f;
#pragma unroll
    for (int j = 0; j < 4; j++) {
        int k = (tid + j * 256) * 4;
        uint2 u = *reinterpret_cast<const uint2*>(vr + k);
        __half2 h0 = *reinterpret_cast<__half2*>(&u.x);
        __half2 h1 = *reinterpret_cast<__half2*>(&u.y);
        float2 f0 = __half22float2(h0);
        float2 f1 = __half22float2(h1);
        vals[j*4+0]=f0.x; vals[j*4+1]=f0.y; vals[j*4+2]=f1.x; vals[j*4+3]=f1.y;
        sum += f0.x+f0.y+f1.x+f1.y;
        sq  += f0.x*f0.x+f0.y*f0.y+f1.x*f1.x+f1.y*f1.y;
    }
    __shared__ float s1[8], s2[8];
#pragma unroll
    for (int o = 16; o; o >>= 1) {
        sum += __shfl_xor_sync(0xffffffffu, sum, o);
        sq  += __shfl_xor_sync(0xffffffffu, sq,  o);
    }
    int warp = tid >> 5, lane = tid & 31;
    if (lane == 0) { s1[warp] = sum; s2[warp] = sq; }
    __syncthreads();
    sum = 0.f; sq = 0.f;
#pragma unroll
    for (int w = 0; w < 8; w++) { sum += s1[w]; sq += s2[w]; }

    float mu   = sum * (1.0f / DIM);
    float var  = sq * (1.0f / DIM) - mu * mu;
    float rstd = rsqrtf(var + LN_EPS);
#pragma unroll
    for (int j = 0; j < 4; j++) {
        int k = (tid + j * 256) * 4;
        float4 g = *reinterpret_cast<const float4*>(ln_g + k);
        float4 bb = *reinterpret_cast<const float4*>(ln_b + k);
        __half2 h0 = __floats2half2_rn((vals[j*4+0]-mu)*rstd*g.x + bb.x,
                                       (vals[j*4+1]-mu)*rstd*g.y + bb.y);
        __half2 h1 = __floats2half2_rn((vals[j*4+2]-mu)*rstd*g.z + bb.z,
                                       (vals[j*4+3]-mu)*rstd*g.w + bb.w);
        uint2 u = {*reinterpret_cast<uint32_t*>(&h0), *reinterpret_cast<uint32_t*>(&h1)};
        *reinterpret_cast<uint2*>(nr + k) = u;
    }
}

// ================= GEMM geometry =============================================
constexpr int BM = 128, BN = 128, BK = 64;
constexpr int STAGES = 3;
constexpr int TILE_B = 128 * 128;
constexpr size_t GEMM_SMEM = (size_t)STAGES * 2 * TILE_B; // 98304

// fused phase: BM=64, stage holds Ah|Al|Bh|Bl
constexpr int FBM = 64;
constexpr int F_A  = FBM * 128;                   // 8192 B per A sub-tile
constexpr int F_B  = NPH * 128;                   // 16384 B per B sub-tile
constexpr int F_STAGE = 2 * F_A + 2 * F_B;        // 49152 B
constexpr int FSTG = 2;
constexpr size_t PH_SMEM = (size_t)FSTG * F_STAGE;    // 98304

// ======== fused phase GEMM: acc = Ah*Bh + Ah*Bl + Al*Bh, split-K x2 ===========
__global__ __launch_bounds__(256, 2) void gemm_phase(
    float* __restrict__ C, int M, int K)
{
    extern __shared__ __align__(128) unsigned char dsmem[];
    uint32_t sb = smem_u32(dsmem);
    // stage s: Ah | Al | Bh | Bl

    int khalf = blockIdx.y;
    C += (size_t)khalf * (size_t)M * NPH;
    const int KH = K / NSEG;                  // 2048
    size_t kbase = (size_t)khalf * KH;

    int tid  = threadIdx.x;
    int warp = tid >> 5;
    int lane = tid & 31;

    int m0 = blockIdx.x * FBM;
    int wm = (warp & 1) * 32;
    int wn = (warp >> 1) * 32;

    int chunk = tid & 7;
    int row0  = tid >> 3;
    const __half* gAh = g_xh   + (size_t)m0 * DIM + kbase + chunk * 8;
    const __half* gAl = g_xl   + (size_t)m0 * DIM + kbase + chunk * 8;
    const __half* gBh = g_wkqh + kbase + chunk * 8;
    const __half* gBl = g_wkql + kbase + chunk * 8;

    auto load_tile = [&](int kt, int stg) {
        size_t koff = (size_t)kt * BK;
        uint32_t base = sb + stg * F_STAGE;
#pragma unroll
        for (int p = 0; p < 2; p++) {        // A: 64 rows each
            int r = row0 + p * 32;
            uint32_t so = r * 128 + ((chunk * 16) ^ ((r & 7) << 4));
            cp_async16s(base + so,       gAh + (size_t)r * DIM + koff);
            cp_async16s(base + F_A + so, gAl + (size_t)r * DIM + koff);
        }
#pragma unroll
        for (int p = 0; p < 4; p++) {        // B: 128 rows each
            int r = row0 + p * 32;
            uint32_t so = r * 128 + ((chunk * 16) ^ ((r & 7) << 4));
            cp_async16s(base + 2 * F_A + so,       gBh + (size_t)r * DIM + koff);
            cp_async16s(base + 2 * F_A + F_B + so, gBl + (size_t)r * DIM + koff);
        }
    };

    int lr = lane & 15;
    int kb = lane >> 4;
    uint32_t xv = (uint32_t)((lr & 7) << 4);
    uint32_t aRow0 = (uint32_t)(wm + lr) * 128;
    uint32_t bRow0 = (uint32_t)(wn + lr) * 128;

    float acc[2][4][4];
#pragma unroll
    for (int i = 0; i < 2; i++)
#pragma unroll
        for (int j = 0; j < 4; j++)
#pragma unroll
            for (int q = 0; q < 4; q++) acc[i][j][q] = 0.f;

    const int nt = KH / BK;   // 32
#pragma unroll
    for (int s = 0; s < FSTG - 1; s++) { load_tile(s, s); cp_commit(); }

    for (int it = 0; it < nt; it++) {
        cp_wait<FSTG - 2>();
        __syncthreads();
        int pre = it + FSTG - 1;
        if (pre < nt) { load_tile(pre, pre % FSTG); cp_commit(); }

        uint32_t base = sb + (it % FSTG) * F_STAGE;
        uint32_t tAh = base, tAl = base + F_A;
        uint32_t tBh = base + 2 * F_A, tBl = tBh + F_B;
#pragma unroll
        for (int s16 = 0; s16 < 4; s16++) {
            uint32_t col = (uint32_t)((s16 * 32 + kb * 16)) ^ xv;
            uint32_t ah[2][4], al[2][4];
#pragma unroll
            for (int mi = 0; mi < 2; mi++) {
                uint32_t off = aRow0 + (uint32_t)(mi * 16 * 128) + col;
                ldmx4(ah[mi][0], ah[mi][1], ah[mi][2], ah[mi][3], tAh + off);
                ldmx4(al[mi][0], al[mi][1], al[mi][2], al[mi][3], tAl + off);
            }
            uint32_t bh[2][4], bl[2][4];
#pragma unroll
            for (int nb = 0; nb < 2; nb++) {
                uint32_t off = bRow0 + (uint32_t)(nb * 16 * 128) + col;
                ldmx4(bh[nb][0], bh[nb][1], bh[nb][2], bh[nb][3], tBh + off);
                ldmx4(bl[nb][0], bl[nb][1], bl[nb][2], bl[nb][3], tBl + off);
            }
#pragma unroll
            for (int mi = 0; mi < 2; mi++)
#pragma unroll
                for (int nb = 0; nb < 2; nb++) {
                    float* c0 = acc[mi][nb * 2 + 0];
                    float* c1 = acc[mi][nb * 2 + 1];
                    // Ah*Bh
                    mma_f16(c0, ah[mi][0], ah[mi][1], ah[mi][2], ah[mi][3], bh[nb][0], bh[nb][2]);
                    mma_f16(c1, ah[mi][0], ah[mi][1], ah[mi][2], ah[mi][3], bh[nb][1], bh[nb][3]);
                    // Ah*Bl
                    mma_f16(c0, ah[mi][0], ah[mi][1], ah[mi][2], ah[mi][3], bl[nb][0], bl[nb][2]);
                    mma_f16(c1, ah[mi][0], ah[mi][1], ah[mi][2], ah[mi][3], bl[nb][1], bl[nb][3]);
                    // Al*Bh
                    mma_f16(c0, al[mi][0], al[mi][1], al[mi][2], al[mi][3], bh[nb][0], bh[nb][2]);
                    mma_f16(c1, al[mi][0], al[mi][1], al[mi][2], al[mi][3], bh[nb][1], bh[nb][3]);
                }
        }
    }
    cp_wait<0>();

    int mrow = m0 + wm + (lane >> 2);
    int ncol = wn + (lane & 3) * 2;
#pragma unroll
    for (int mi = 0; mi < 2; mi++) {
#pragma unroll
        for (int nj = 0; nj < 4; nj++) {
            int n = ncol + nj * 8;
            size_t go0 = (size_t)(mrow + mi * 16)     * NPH + n;
            size_t go1 = (size_t)(mrow + mi * 16 + 8) * NPH + n;
            *reinterpret_cast<float2*>(C + go0) = {acc[mi][nj][0], acc[mi][nj][1]};
            *reinterpret_cast<float2*>(C + go1) = {acc[mi][nj][2], acc[mi][nj][3]};
        }
    }
}

// ======== big GEMM: raw mma.sync fp16, 128x128, 2 CTA/SM =====================
// MODE 1: Cf[go] = acc + bias[n] + (float)addend_h[go]
// MODE 2: Ch[go] = (__half)((acc + bias[n]) * coef[m])
template <int MODE>
__global__ __launch_bounds__(256, 2) void gemm_big(
    const __half* __restrict__ A, const __half* __restrict__ Bw,
    float* __restrict__ Cf, __half* __restrict__ Ch, int M, int N, int K,
    const float* __restrict__ bias, const __half* __restrict__ addend_h,
    const float* __restrict__ coef)
{
    extern __shared__ __align__(128) unsigned char dsmem[];
    uint32_t sb = smem_u32(dsmem);
    uint32_t sA = sb;
    uint32_t sB = sb + STAGES * TILE_B;

    int tid  = threadIdx.x;
    int warp = tid >> 5;
    int lane = tid & 31;

    const int num_m = M / BM, num_n = N / BN;
    const int GROUP = 8;
    int id = blockIdx.x;
    int group_size = GROUP * num_n;
    int gid = id / group_size;
    int first_m = gid * GROUP;
    int gm_sz = (num_m - first_m) < GROUP ? (num_m - first_m) : GROUP;
    int pid_m = first_m + (id % group_size) % gm_sz;
    int pid_n = (id % group_size) / gm_sz;
    int m0 = pid_m * BM;
    int n0 = pid_n * BN;

    int wm = (warp & 3) * 32;
    int wn = (warp >> 2) * 64;

    int chunk = tid & 7;
    int row0  = tid >> 3;
    const __half* gA = A  + (size_t)m0 * K + chunk * 8;
    const __half* gB = Bw + (size_t)n0 * K + chunk * 8;

    auto load_tile = [&](int kt, int stg) {
        size_t koff = (size_t)kt * BK;
        uint32_t dA = sA + stg * TILE_B;
        uint32_t dB = sB + stg * TILE_B;
#pragma unroll
        for (int p = 0; p < 4; p++) {
            int r = row0 + p * 32;
            uint32_t so = r * 128 + ((chunk * 16) ^ ((r & 7) << 4));
            cp_async16s(dA + so, gA + (size_t)r * K + koff);
            cp_async16s(dB + so, gB + (size_t)r * K + koff);
        }
    };

    int lr = lane & 15;
    int kb = lane >> 4;
    uint32_t xv = (uint32_t)((lr & 7) << 4);
    uint32_t aRow0 = (uint32_t)(wm + lr) * 128;
    uint32_t bRow0 = (uint32_t)(wn + lr) * 128;

    float acc[2][8][4];
#pragma unroll
    for (int i = 0; i < 2; i++)
#pragma unroll
        for (int j = 0; j < 8; j++)
#pragma unroll
            for (int q = 0; q < 4; q++) acc[i][j][q] = 0.f;

    const int nt = K / BK;
#pragma unroll
    for (int s = 0; s < STAGES - 1; s++) { load_tile(s, s); cp_commit(); }

    for (int it = 0; it < nt; it++) {
        cp_wait<STAGES - 2>();
        __syncthreads();
        int pre = it + STAGES - 1;
        if (pre < nt) { load_tile(pre, pre % STAGES); cp_commit(); }

        uint32_t tA = sA + (it % STAGES) * TILE_B;
        uint32_t tB = sB + (it % STAGES) * TILE_B;
#pragma unroll
        for (int s16 = 0; s16 < 4; s16++) {
            uint32_t col = (uint32_t)((s16 * 32 + kb * 16)) ^ xv;
            uint32_t a[2][4];
#pragma unroll
            for (int mi = 0; mi < 2; mi++)
                ldmx4(a[mi][0], a[mi][1], a[mi][2], a[mi][3],
                      tA + aRow0 + (uint32_t)(mi * 16 * 128) + col);
            uint32_t b[4][4];
#pragma unroll
            for (int nb = 0; nb < 4; nb++)
                ldmx4(b[nb][0], b[nb][1], b[nb][2], b[nb][3],
                      tB + bRow0 + (uint32_t)(nb * 16 * 128) + col);
#pragma unroll
            for (int mi = 0; mi < 2; mi++)
#pragma unroll
                for (int nb = 0; nb < 4; nb++) {
                    mma_f16(acc[mi][nb * 2 + 0], a[mi][0], a[mi][1], a[mi][2], a[mi][3],
                            b[nb][0], b[nb][2]);
                    mma_f16(acc[mi][nb * 2 + 1], a[mi][0], a[mi][1], a[mi][2], a[mi][3],
                            b[nb][1], b[nb][3]);
                }
        }
    }
    cp_wait<0>();

    int mrow = m0 + wm + (lane >> 2);
    int ncol = n0 + wn + (lane & 3) * 2;
#pragma unroll
    for (int mi = 0; mi < 2; mi++) {
        float cf0 = 0.f, cf1 = 0.f;
        if (MODE == 2) {
            cf0 = coef[mrow + mi * 16];
            cf1 = coef[mrow + mi * 16 + 8];
        }
#pragma unroll
        for (int nj = 0; nj < 8; nj++) {
            int n = ncol + nj * 8;
            size_t go0 = (size_t)(mrow + mi * 16)     * N + n;
            size_t go1 = (size_t)(mrow + mi * 16 + 8) * N + n;
            float2 bb = *reinterpret_cast<const float2*>(bias + n);
            if (MODE == 1) {
                float2 a0 = __half22float2(*reinterpret_cast<const __half2*>(addend_h + go0));
                float2 a1 = __half22float2(*reinterpret_cast<const __half2*>(addend_h + go1));
                float2 v0 = {acc[mi][nj][0] + bb.x + a0.x, acc[mi][nj][1] + bb.y + a0.y};
                float2 v1 = {acc[mi][nj][2] + bb.x + a1.x, acc[mi][nj][3] + bb.y + a1.y};
                *reinterpret_cast<float2*>(Cf + go0) = v0;
                *reinterpret_cast<float2*>(Cf + go1) = v1;
            } else {
                __half2 h0 = __floats2half2_rn((acc[mi][nj][0] + bb.x) * cf0,
                                               (acc[mi][nj][1] + bb.y) * cf0);
                __half2 h1 = __floats2half2_rn((acc[mi][nj][2] + bb.x) * cf1,
                                               (acc[mi][nj][3] + bb.y) * cf1);
                *reinterpret_cast<__half2*>(Ch + go0) = h0;
                *reinterpret_cast<__half2*>(Ch + go1) = h1;
            }
        }
    }
}

// ---------------- launch -----------------------------------------------------
extern "C" void kernel_launch(void* const* d_in, const int* in_sizes, int n_in,
                              void* d_out, int out_size) {
    const float* x    = (const float*)d_in[0];
    const float* Wk   = (const float*)d_in[1];
    const float* bk   = (const float*)d_in[2];
    const float* Wq   = (const float*)d_in[3];
    const float* bq   = (const float*)d_in[4];
    const float* Wv   = (const float*)d_in[5];
    const float* bv   = (const float*)d_in[6];
    const float* ln_g = (const float*)d_in[7];
    const float* ln_b = (const float*)d_in[8];
    const float* Wo   = (const float*)d_in[9];
    const float* bo   = (const float*)d_in[10];
    float* out = (float*)d_out;

    __half *p_xh, *p_wvh, *p_woh, *p_vh, *p_nh;
    float *p_phase, *p_coef;
    cudaGetSymbolAddress((void**)&p_xh,   g_xh);
    cudaGetSymbolAddress((void**)&p_wvh,  g_wvh);
    cudaGetSymbolAddress((void**)&p_woh,  g_woh);
    cudaGetSymbolAddress((void**)&p_vh,   g_vh);
    cudaGetSymbolAddress((void**)&p_nh,   g_nh);
    cudaGetSymbolAddress((void**)&p_phase, g_phase);
    cudaGetSymbolAddress((void**)&p_coef,  g_coef);

    cudaFuncSetAttribute((const void*)gemm_phase,
                         cudaFuncAttributeMaxDynamicSharedMemorySize, (int)PH_SMEM);
    cudaFuncSetAttribute((const void*)gemm_big<1>,
                         cudaFuncAttributeMaxDynamicSharedMemorySize, (int)GEMM_SMEM);
    cudaFuncSetAttribute((const void*)gemm_big<2>,
                         cudaFuncAttributeMaxDynamicSharedMemorySize, (int)GEMM_SMEM);

    // prep (3 launches)
    size_t nx = (size_t)B_ROWS * DIM / 4;
    prep_x<<<(unsigned)((nx + 255) / 256), 256>>>(x, nx);                          // 1
    size_t nw = (size_t)DIM * DIM / 4;
    conv_w2<<<(unsigned)((2 * nw + 255) / 256), 256>>>(Wv, Wo, nw);                // 2
    size_t nk = (size_t)64 * DIM / 4;
    split2_kq<<<(unsigned)((2 * nk + 255) / 256), 256>>>(Wk, Wq, nk);              // 3

    // fused phase scores (split-K x2) -> coef
    gemm_phase<<<dim3(B_ROWS / FBM, NSEG), 256, PH_SMEM>>>(p_phase, B_ROWS, DIM);  // 4
    coef_kernel<<<B_ROWS / 8, 256>>>(bk, bq);                                      // 5

    // V path: g_vh = (x @ Wv^T + bv) * coef   (fp16)
    gemm_big<2><<<(B_ROWS / BM) * (DIM / BN), 256, GEMM_SMEM>>>(
        p_xh, p_wvh, nullptr, p_vh, B_ROWS, DIM, DIM, bv, nullptr, p_coef);        // 6

    // LayerNorm -> fp16 normed
    ln_kernel<<<B_ROWS, 256>>>(ln_g, ln_b);                                        // 7

    // out = x + normed @ Wo^T + bo   (x residual read as fp16)
    gemm_big<1><<<(B_ROWS / BM) * (DIM / BN), 256, GEMM_SMEM>>>(
        p_nh, p_woh, out, nullptr, B_ROWS, DIM, DIM, bo, p_xh, nullptr);           // 8
}